// round 1
// baseline (speedup 1.0000x reference)
#include <cuda_runtime.h>

// ConvLSTM2D, B=8 T=16 H=64 W=64 Cin=32 F=64, relu / hard_sigmoid,
// return final hidden state (8,64,64,64) fp32.
//
// Per timestep: z = conv3x3(x_t, W) + conv3x3(h, U) + b  -> gates -> h,c update.
// Implemented as implicit GEMM: M=32768 pixels, N=256 channels, K=288 (+576).

#define kB   8
#define kT   16
#define kH   64
#define kW   64
#define kCin 32
#define kF   64
#define kG   256          // 4*F
#define kNPix 32768       // B*H*W

// Scratch (allocation-free rule: __device__ globals)
__device__ float g_z[(size_t)kNPix * kG];   // 33.5 MB  z for current step
__device__ float g_h[(size_t)kNPix * kF];   // hidden state
__device__ float g_c[(size_t)kNPix * kF];   // cell state

// ---------------------------------------------------------------------------
// GEMM: z[m, n] = bias[n] + sum_k patch(m,k) * Wgt[k,n]    (two phases: x, h)
// Tile: BM=128, BN=128, Kc=16, 256 threads, 8x8 per-thread micro-tile.
// ---------------------------------------------------------------------------

__device__ __forceinline__ void load_slab(
    const float* __restrict__ src, const float* __restrict__ wgt,
    int Cin, size_t bstride, int k0, int buf, int m_tile, int n0, int tid,
    float As[2][16][128], float Bs[2][16][128])
{
    // Within a 16-wide K slab, (ky,kx) is constant (16 divides both 32 and 64).
    const int kpos = k0 / Cin;            // 0..8 -> (ky,kx)
    const int cin0 = k0 - kpos * Cin;
    const int dy = kpos / 3 - 1;
    const int dx = kpos - (kpos / 3) * 3 - 1;

    // A: 128 pixels x 16 k, transposed into As[k][m]
#pragma unroll
    for (int i = 0; i < 2; i++) {
        int li = tid + i * 256;           // 0..511
        int m  = li >> 2;                 // 0..127
        int kg = li & 3;                  // float4 group within slab
        int pm = m_tile + m;
        int bb  = pm >> 12;               // / (H*W)
        int rem = pm & 4095;
        int y  = (rem >> 6) + dy;
        int xw = (rem & 63) + dx;
        float4 v = make_float4(0.f, 0.f, 0.f, 0.f);
        if ((unsigned)y < 64u && (unsigned)xw < 64u) {
            v = *(const float4*)(src + (size_t)bb * bstride
                                 + (size_t)((y << 6) + xw) * Cin + cin0 + (kg << 2));
        }
        As[buf][kg * 4 + 0][m] = v.x;
        As[buf][kg * 4 + 1][m] = v.y;
        As[buf][kg * 4 + 2][m] = v.z;
        As[buf][kg * 4 + 3][m] = v.w;
    }
    // B: 16 k x 128 n, weights are (ky,kx,cin,cout) row-major -> [k][n] directly
#pragma unroll
    for (int i = 0; i < 2; i++) {
        int li = tid + i * 256;
        int kr = li >> 5;                 // 0..15
        int ng = (li & 31) << 2;          // 0..124 step 4
        *(float4*)&Bs[buf][kr][ng] =
            *(const float4*)(wgt + (size_t)(k0 + kr) * kG + n0 + ng);
    }
}

__global__ __launch_bounds__(256, 2)
void zconv_kernel(const float* __restrict__ x, const float* __restrict__ Wp,
                  const float* __restrict__ Up, const float* __restrict__ bias,
                  int t, int use_h)
{
    __shared__ __align__(16) float As[2][16][128];
    __shared__ __align__(16) float Bs[2][16][128];

    const int tid = threadIdx.x;
    const int tx = tid & 15;              // -> 8 output channels
    const int ty = tid >> 4;              // -> 8 output pixels
    const int m_tile = blockIdx.x * 128;
    const int n0 = blockIdx.y * 128;

    float acc[8][8];
#pragma unroll
    for (int r = 0; r < 8; r++)
#pragma unroll
        for (int j = 0; j < 8; j++) acc[r][j] = 0.f;

    const int nphase = use_h ? 2 : 1;
    for (int phase = 0; phase < nphase; phase++) {
        const float* src;
        const float* wgt;
        int Cin, NS;
        size_t bstride;
        if (phase == 0) {
            src = x + (size_t)t * (kH * kW * kCin);       // x[:, t] slice
            wgt = Wp; Cin = kCin; NS = (9 * kCin) / 16;   // 18 slabs
            bstride = (size_t)kT * kH * kW * kCin;        // batch stride of x
        } else {
            src = g_h; wgt = Up; Cin = kF; NS = (9 * kF) / 16;  // 36 slabs
            bstride = (size_t)kH * kW * kF;
        }

        load_slab(src, wgt, Cin, bstride, 0, 0, m_tile, n0, tid, As, Bs);
        __syncthreads();

        for (int s = 0; s < NS; s++) {
            const int cur = s & 1;
            if (s + 1 < NS)
                load_slab(src, wgt, Cin, bstride, (s + 1) * 16, cur ^ 1,
                          m_tile, n0, tid, As, Bs);
#pragma unroll
            for (int k = 0; k < 16; k++) {
                float4 a0 = *(const float4*)&As[cur][k][ty * 4];
                float4 a1 = *(const float4*)&As[cur][k][64 + ty * 4];
                float4 b0 = *(const float4*)&Bs[cur][k][tx * 4];
                float4 b1 = *(const float4*)&Bs[cur][k][64 + tx * 4];
                float av[8] = {a0.x, a0.y, a0.z, a0.w, a1.x, a1.y, a1.z, a1.w};
                float bv[8] = {b0.x, b0.y, b0.z, b0.w, b1.x, b1.y, b1.z, b1.w};
#pragma unroll
                for (int r = 0; r < 8; r++)
#pragma unroll
                    for (int j = 0; j < 8; j++)
                        acc[r][j] = fmaf(av[r], bv[j], acc[r][j]);
            }
            __syncthreads();
        }
    }

    // Epilogue: + bias, write z
    float4 bi0 = *(const float4*)&bias[n0 + tx * 4];
    float4 bi1 = *(const float4*)&bias[n0 + 64 + tx * 4];
#pragma unroll
    for (int r = 0; r < 8; r++) {
        int ml = (r < 4) ? (ty * 4 + r) : (64 + ty * 4 + (r - 4));
        float* zr = g_z + (size_t)(m_tile + ml) * kG + n0;
        float4 o0 = make_float4(acc[r][0] + bi0.x, acc[r][1] + bi0.y,
                                acc[r][2] + bi0.z, acc[r][3] + bi0.w);
        float4 o1 = make_float4(acc[r][4] + bi1.x, acc[r][5] + bi1.y,
                                acc[r][6] + bi1.z, acc[r][7] + bi1.w);
        *(float4*)&zr[tx * 4] = o0;
        *(float4*)&zr[64 + tx * 4] = o1;
    }
}

// ---------------------------------------------------------------------------
// Gate update: i,f,o = hard_sigmoid(z*), c' = f*c + i*relu(zc), h' = o*relu(c')
// hard_sigmoid(x) = relu6(x+3)/6  (exact Keras/jax.nn.hard_sigmoid)
// ---------------------------------------------------------------------------

__device__ __forceinline__ float hsig(float v) {
    return fminf(fmaxf(v + 3.f, 0.f), 6.f) * (1.f / 6.f);
}

__global__ void gate_kernel(float* __restrict__ out, int use_c, int last)
{
    int idx = blockIdx.x * blockDim.x + threadIdx.x;   // 0 .. NPix*F-1
    int m = idx >> 6;
    int c = idx & 63;
    const float* zr = g_z + (size_t)m * kG;
    float zi = zr[c];
    float zf = zr[64 + c];
    float zc = zr[128 + c];
    float zo = zr[192 + c];
    float cp = use_c ? g_c[idx] : 0.f;
    float gi = hsig(zi);
    float gf = hsig(zf);
    float go = hsig(zo);
    float cn = gf * cp + gi * fmaxf(zc, 0.f);
    float hn = go * fmaxf(cn, 0.f);
    g_c[idx] = cn;
    if (last) out[idx] = hn;
    else      g_h[idx] = hn;
}

// ---------------------------------------------------------------------------

extern "C" void kernel_launch(void* const* d_in, const int* in_sizes, int n_in,
                              void* d_out, int out_size)
{
    const float* x    = (const float*)d_in[0];   // (8,16,64,64,32)
    const float* Wp   = (const float*)d_in[1];   // (3,3,32,256)
    const float* Up   = (const float*)d_in[2];   // (3,3,64,256)
    const float* bias = (const float*)d_in[3];   // (256,)
    float* out = (float*)d_out;                  // (8,64,64,64)

    dim3 ggrid(kNPix / 128, kG / 128);           // (256, 2)
    const int gate_blocks = (kNPix * kF) / 256;  // 8192

    for (int t = 0; t < kT; t++) {
        zconv_kernel<<<ggrid, 256>>>(x, Wp, Up, bias, t, t > 0 ? 1 : 0);
        gate_kernel<<<gate_blocks, 256>>>(out, t > 0 ? 1 : 0, t == kT - 1 ? 1 : 0);
    }
}

// round 2
// speedup vs baseline: 1.6633x; 1.6633x over previous
#include <cuda_runtime.h>

// ConvLSTM2D, B=8 T=16 H=64 W=64 Cin=32 F=64, relu / hard_sigmoid,
// return final hidden state (8,64,64,64) fp32.
//
// Per timestep: z = conv3x3(x_t, W) + conv3x3(h, U) + b  -> gates -> h,c update.
// Implicit GEMM (M=32768, N=256, K=288+576) with packed fma.rn.f32x2
// (Blackwell dual-pumped fp32: 2 FMAs per issued instruction).

#define kB   8
#define kT   16
#define kH   64
#define kW   64
#define kCin 32
#define kF   64
#define kG   256          // 4*F
#define kNPix 32768       // B*H*W

// Scratch (allocation-free rule: __device__ globals)
__device__ float g_z[(size_t)kNPix * kG];   // 33.5 MB  z for current step
__device__ float g_h[(size_t)kNPix * kF];   // hidden state
__device__ float g_c[(size_t)kNPix * kF];   // cell state

// ---- packed f32x2 helpers --------------------------------------------------

__device__ __forceinline__ void fma2(unsigned long long& d,
                                     unsigned long long a,
                                     unsigned long long b) {
    asm("fma.rn.f32x2 %0, %1, %2, %3;" : "=l"(d) : "l"(a), "l"(b), "l"(d));
}
__device__ __forceinline__ unsigned long long pk2(float v) {  // (v, v)
    unsigned long long r;
    asm("mov.b64 %0, {%1, %1};" : "=l"(r) : "f"(v));
    return r;
}
__device__ __forceinline__ void upk(unsigned long long v, float& lo, float& hi) {
    asm("mov.b64 {%0, %1}, %2;" : "=f"(lo), "=f"(hi) : "l"(v));
}

// ---------------------------------------------------------------------------
// GEMM: z[m, n] = bias[n] + sum_k patch(m,k) * Wgt[k,n]    (two phases: x, h)
// Tile: BM=128, BN=128, Kc=16, 256 threads, 8x8 per-thread micro-tile.
// ---------------------------------------------------------------------------

__device__ __forceinline__ void load_slab(
    const float* __restrict__ src, const float* __restrict__ wgt,
    int Cin, size_t bstride, int k0, int buf, int m_tile, int n0, int tid,
    float As[2][16][128], float Bs[2][16][128])
{
    // Within a 16-wide K slab, (ky,kx) is constant (16 divides both 32 and 64).
    const int kpos = k0 / Cin;            // 0..8 -> (ky,kx)
    const int cin0 = k0 - kpos * Cin;
    const int dy = kpos / 3 - 1;
    const int dx = kpos - (kpos / 3) * 3 - 1;

    // A: 128 pixels x 16 k, transposed into As[k][m]
#pragma unroll
    for (int i = 0; i < 2; i++) {
        int li = tid + i * 256;           // 0..511
        int m  = li >> 2;                 // 0..127
        int kg = li & 3;                  // float4 group within slab
        int pm = m_tile + m;
        int bb  = pm >> 12;               // / (H*W)
        int rem = pm & 4095;
        int y  = (rem >> 6) + dy;
        int xw = (rem & 63) + dx;
        float4 v = make_float4(0.f, 0.f, 0.f, 0.f);
        if ((unsigned)y < 64u && (unsigned)xw < 64u) {
            v = *(const float4*)(src + (size_t)bb * bstride
                                 + (size_t)((y << 6) + xw) * Cin + cin0 + (kg << 2));
        }
        As[buf][kg * 4 + 0][m] = v.x;
        As[buf][kg * 4 + 1][m] = v.y;
        As[buf][kg * 4 + 2][m] = v.z;
        As[buf][kg * 4 + 3][m] = v.w;
    }
    // B: 16 k x 128 n, weights are (ky,kx,cin,cout) row-major -> [k][n] directly
#pragma unroll
    for (int i = 0; i < 2; i++) {
        int li = tid + i * 256;
        int kr = li >> 5;                 // 0..15
        int ng = (li & 31) << 2;          // 0..124 step 4
        *(float4*)&Bs[buf][kr][ng] =
            *(const float4*)(wgt + (size_t)(k0 + kr) * kG + n0 + ng);
    }
}

__global__ __launch_bounds__(256, 2)
void zconv_kernel(const float* __restrict__ x, const float* __restrict__ Wp,
                  const float* __restrict__ Up, const float* __restrict__ bias,
                  int t, int use_h)
{
    __shared__ __align__(16) float As[2][16][128];
    __shared__ __align__(16) float Bs[2][16][128];

    const int tid = threadIdx.x;
    const int tx = tid & 15;              // -> 8 output channels (4 f32x2 pairs)
    const int ty = tid >> 4;              // -> 8 output pixels
    const int m_tile = blockIdx.x * 128;
    const int n0 = blockIdx.y * 128;

    // acc[r][j] holds the f32x2 pair for pixel r, channel-pair j
    unsigned long long acc[8][4];
#pragma unroll
    for (int r = 0; r < 8; r++)
#pragma unroll
        for (int j = 0; j < 4; j++) acc[r][j] = 0ull;   // (+0.f, +0.f)

    const int nphase = use_h ? 2 : 1;
    for (int phase = 0; phase < nphase; phase++) {
        const float* src;
        const float* wgt;
        int Cin, NS;
        size_t bstride;
        if (phase == 0) {
            src = x + (size_t)t * (kH * kW * kCin);       // x[:, t] slice
            wgt = Wp; Cin = kCin; NS = (9 * kCin) / 16;   // 18 slabs
            bstride = (size_t)kT * kH * kW * kCin;        // batch stride of x
        } else {
            src = g_h; wgt = Up; Cin = kF; NS = (9 * kF) / 16;  // 36 slabs
            bstride = (size_t)kH * kW * kF;
        }

        load_slab(src, wgt, Cin, bstride, 0, 0, m_tile, n0, tid, As, Bs);
        __syncthreads();

        for (int s = 0; s < NS; s++) {
            const int cur = s & 1;
            if (s + 1 < NS)
                load_slab(src, wgt, Cin, bstride, (s + 1) * 16, cur ^ 1,
                          m_tile, n0, tid, As, Bs);
#pragma unroll
            for (int k = 0; k < 16; k++) {
                float4 a0 = *(const float4*)&As[cur][k][ty * 4];
                float4 a1 = *(const float4*)&As[cur][k][64 + ty * 4];
                // Bs holds consecutive n: a float4 is already two f32x2 pairs
                ulonglong2 bq0 = *(const ulonglong2*)&Bs[cur][k][tx * 4];
                ulonglong2 bq1 = *(const ulonglong2*)&Bs[cur][k][64 + tx * 4];
                unsigned long long bv[4] = {bq0.x, bq0.y, bq1.x, bq1.y};
                unsigned long long av[8] = {
                    pk2(a0.x), pk2(a0.y), pk2(a0.z), pk2(a0.w),
                    pk2(a1.x), pk2(a1.y), pk2(a1.z), pk2(a1.w)};
#pragma unroll
                for (int r = 0; r < 8; r++)
#pragma unroll
                    for (int j = 0; j < 4; j++)
                        fma2(acc[r][j], av[r], bv[j]);
            }
            __syncthreads();
        }
    }

    // Epilogue: + bias, write z
    float4 bi0 = *(const float4*)&bias[n0 + tx * 4];
    float4 bi1 = *(const float4*)&bias[n0 + 64 + tx * 4];
#pragma unroll
    for (int r = 0; r < 8; r++) {
        int ml = (r < 4) ? (ty * 4 + r) : (64 + ty * 4 + (r - 4));
        float* zr = g_z + (size_t)(m_tile + ml) * kG + n0;
        float4 o0, o1;
        upk(acc[r][0], o0.x, o0.y);
        upk(acc[r][1], o0.z, o0.w);
        upk(acc[r][2], o1.x, o1.y);
        upk(acc[r][3], o1.z, o1.w);
        o0.x += bi0.x; o0.y += bi0.y; o0.z += bi0.z; o0.w += bi0.w;
        o1.x += bi1.x; o1.y += bi1.y; o1.z += bi1.z; o1.w += bi1.w;
        *(float4*)&zr[tx * 4] = o0;
        *(float4*)&zr[64 + tx * 4] = o1;
    }
}

// ---------------------------------------------------------------------------
// Gate update: i,f,o = hard_sigmoid(z*), c' = f*c + i*relu(zc), h' = o*relu(c')
// hard_sigmoid(x) = relu6(x+3)/6  (exact Keras/jax.nn.hard_sigmoid)
// ---------------------------------------------------------------------------

__device__ __forceinline__ float hsig(float v) {
    return fminf(fmaxf(v + 3.f, 0.f), 6.f) * (1.f / 6.f);
}

__global__ void gate_kernel(float* __restrict__ out, int use_c, int last)
{
    int idx = blockIdx.x * blockDim.x + threadIdx.x;   // 0 .. NPix*F-1
    int m = idx >> 6;
    int c = idx & 63;
    const float* zr = g_z + (size_t)m * kG;
    float zi = zr[c];
    float zf = zr[64 + c];
    float zc = zr[128 + c];
    float zo = zr[192 + c];
    float cp = use_c ? g_c[idx] : 0.f;
    float gi = hsig(zi);
    float gf = hsig(zf);
    float go = hsig(zo);
    float cn = gf * cp + gi * fmaxf(zc, 0.f);
    float hn = go * fmaxf(cn, 0.f);
    g_c[idx] = cn;
    if (last) out[idx] = hn;
    else      g_h[idx] = hn;
}

// ---------------------------------------------------------------------------

extern "C" void kernel_launch(void* const* d_in, const int* in_sizes, int n_in,
                              void* d_out, int out_size)
{
    const float* x    = (const float*)d_in[0];   // (8,16,64,64,32)
    const float* Wp   = (const float*)d_in[1];   // (3,3,32,256)
    const float* Up   = (const float*)d_in[2];   // (3,3,64,256)
    const float* bias = (const float*)d_in[3];   // (256,)
    float* out = (float*)d_out;                  // (8,64,64,64)

    dim3 ggrid(kNPix / 128, kG / 128);           // (256, 2)
    const int gate_blocks = (kNPix * kF) / 256;  // 8192

    for (int t = 0; t < kT; t++) {
        zconv_kernel<<<ggrid, 256>>>(x, Wp, Up, bias, t, t > 0 ? 1 : 0);
        gate_kernel<<<gate_blocks, 256>>>(out, t > 0 ? 1 : 0, t == kT - 1 ? 1 : 0);
    }
}

// round 7
// speedup vs baseline: 3.0620x; 1.8409x over previous
#include <cuda_runtime.h>
#include <cuda_fp16.h>
#include <cstdint>

// ConvLSTM2D via mma.sync fp16 (baseline PTX) with fp16 x2 3-product split.
// Split baked into interleaved-channel images:
//   g_xs: 96 ch  = [xh | xh | xl],  weights B' = [Wh | Wl | Wh]
//   g_hs: 192 ch = [hh | hh | hl],  weights B' = [Uh | Ul | Uh]
// z = xh*Wh + xh*Wl + xl*Wh + hh*Uh + hh*Ul + hl*Uh.
//
// h-state is PING-PONG double-buffered: step t reads g_hs[t&1] and writes
// g_hs[(t&1)^1]. Without this, a fast CTA's epilogue overwrites h_{t-1}
// halo pixels that slower CTAs are still reading (the rounds-3..6 bug).

#define kT    16
#define kNPix 32768
#define KX2   896        // x K-part: 9*96=864, padded to 896
#define KALL2 2624       // 896 + 9*192
#define NS_ALL 41
#define NS_X   14

// -------- device scratch (allocation-free rule) -----------------------------
__device__ __half g_xs[(size_t)8 * 16 * 4096 * 96];      // 100.7 MB
__device__ __half g_hs[2][(size_t)kNPix * 192];          // 2 x 12.6 MB
__device__ float  g_c [(size_t)kNPix * 64];              // 8.4 MB
__device__ __half g_Wb[(size_t)256 * KALL2];             // 1.35 MB
__device__ __align__(16) __half g_zeros[8];              // stays zero

// -------- helpers -----------------------------------------------------------
__device__ __forceinline__ uint32_t sm_u32(const void* p) {
    return (uint32_t)__cvta_generic_to_shared(p);
}
__device__ __forceinline__ uint32_t swz(uint32_t o) { return o ^ ((o >> 3) & 0x70); }

__device__ __forceinline__ void cp16(uint32_t dst, const void* src) {
    asm volatile("cp.async.cg.shared.global [%0], [%1], 16;"
                 :: "r"(dst), "l"(src));
}
__device__ __forceinline__ void cp_commit() {
    asm volatile("cp.async.commit_group;" ::: "memory");
}
__device__ __forceinline__ void cp_wait0() {
    asm volatile("cp.async.wait_group 0;" ::: "memory");
}
__device__ __forceinline__ void ldsm4(uint32_t* r, uint32_t a) {
    asm volatile("ldmatrix.sync.aligned.m8n8.x4.shared.b16 {%0,%1,%2,%3}, [%4];"
                 : "=r"(r[0]), "=r"(r[1]), "=r"(r[2]), "=r"(r[3]) : "r"(a));
}
__device__ __forceinline__ void mma16816(float* c, const uint32_t* a,
                                         const uint32_t* b) {
    asm volatile(
        "mma.sync.aligned.m16n8k16.row.col.f32.f16.f16.f32 "
        "{%0,%1,%2,%3}, {%4,%5,%6,%7}, {%8,%9}, {%0,%1,%2,%3};"
        : "+f"(c[0]), "+f"(c[1]), "+f"(c[2]), "+f"(c[3])
        : "r"(a[0]), "r"(a[1]), "r"(a[2]), "r"(a[3]), "r"(b[0]), "r"(b[1]));
}
__device__ __forceinline__ float hsig(float v) {
    return fminf(fmaxf(v + 3.f, 0.f), 6.f) * (1.f / 6.f);
}

// -------- precompute: B' weights in interleaved K order ----------------------
__global__ void wb_kernel(const float* __restrict__ W, const float* __restrict__ U)
{
    int k_all = blockIdx.x;      // 0..KALL2-1
    int n = threadIdx.x;         // 0..255
    float v = 0.f;
    int sub = 0;
    bool valid = false;
    if (k_all < KX2) {
        if (k_all < 864) {
            int tap = k_all / 96, r = k_all % 96;
            sub = r / 32;
            int cin = r % 32;
            v = W[(size_t)(tap * 32 + cin) * 256 + n];
            valid = true;
        }
    } else {
        int k = k_all - KX2;
        int tap = k / 192, r = k % 192;
        sub = r / 64;
        int cin = r % 64;
        v = U[(size_t)(tap * 64 + cin) * 256 + n];
        valid = true;
    }
    __half o = __float2half(0.f);
    if (valid) {
        __half hi = __float2half(v);
        o = (sub == 1) ? __float2half(v - __half2float(hi)) : hi;
    }
    g_Wb[(size_t)n * KALL2 + k_all] = o;
}

// -------- precompute: x split image ------------------------------------------
__global__ void xs_kernel(const float* __restrict__ x)
{
    size_t i = (size_t)blockIdx.x * blockDim.x + threadIdx.x;  // 16.7M
    int cin = (int)(i & 31);
    size_t p = i >> 5;
    float v = x[i];
    __half hi = __float2half(v);
    __half lo = __float2half(v - __half2float(hi));
    g_xs[p * 96 + cin]      = hi;
    g_xs[p * 96 + 32 + cin] = hi;
    g_xs[p * 96 + 64 + cin] = lo;
}

// -------- main step kernel ---------------------------------------------------
// 256 CTAs x 512 threads; CTA = 128 pixels x 256 gates; 16 warps = 4(M)x4(N),
// warp tile 32x64. Dynamic smem: A[2] 16KB @0/16K, B[2] 32KB @32K/64K.

__global__ __launch_bounds__(512, 1)
void lstm_step_kernel(const float* __restrict__ bias, float* __restrict__ out,
                      int t, int last)
{
    extern __shared__ __align__(16) char dsm_raw[];
    __shared__ float s_bias[256];

    const int tid = threadIdx.x;
    const int wid = tid >> 5;
    const int lane = tid & 31;
    const int m_tile = blockIdx.x * 128;

    const uint32_t dyn = sm_u32(dsm_raw);
    const uint32_t base = (dyn + 1023) & ~1023u;
    char* dptr = dsm_raw + (base - dyn);

    if (tid < 64) ((float4*)s_bias)[tid] = ((const float4*)bias)[tid];

    const int NS = (t == 0) ? NS_X : NS_ALL;
    const __half* h_rd = g_hs[t & 1];          // h_{t-1}
    __half*       h_wr = g_hs[(t & 1) ^ 1];    // h_t

    auto load_slab = [&](int s, int buf) {
        const uint32_t abuf = base + buf * 16384;
        const uint32_t bbuf = base + 32768 + buf * 32768;
        // A: 1024 16B chunks (128 rows x 8 kgroups), 2 per thread
#pragma unroll
        for (int i = 0; i < 2; i++) {
            int c = tid + i * 512;
            int m = c >> 3, kg = c & 7;
            int k0 = s * 64 + kg * 8;
            int p = m_tile + m;
            int bb = p >> 12, rem = p & 4095, py = rem >> 6, px = rem & 63;
            const __half* src = g_zeros;
            if (k0 < KX2) {
                if (k0 < 864) {
                    int tap = k0 / 96, ch = k0 % 96;   // ch multiple of 8
                    int y = py + tap / 3 - 1, xw = px + tap % 3 - 1;
                    if ((unsigned)y < 64u && (unsigned)xw < 64u)
                        src = g_xs + ((size_t)((bb * 16 + t) * 4096
                                               + (y << 6) + xw)) * 96 + ch;
                }
            } else {
                int k = k0 - KX2;
                int tap = k / 192, ch = k % 192;        // ch multiple of 8
                int y = py + tap / 3 - 1, xw = px + tap % 3 - 1;
                if ((unsigned)y < 64u && (unsigned)xw < 64u)
                    src = h_rd + ((size_t)((bb << 12) + (y << 6) + xw)) * 192 + ch;
            }
            cp16(abuf + swz((uint32_t)(m * 128 + kg * 16)), src);
        }
        // B: 2048 16B chunks (256 rows x 8 kgroups), 4 per thread
#pragma unroll
        for (int i = 0; i < 4; i++) {
            int c = tid + i * 512;
            int n = c >> 3, kg = c & 7;
            cp16(bbuf + swz((uint32_t)(n * 128 + kg * 16)),
                 g_Wb + (size_t)n * KALL2 + s * 64 + kg * 8);
        }
    };

    // accumulators: 2 m-subtiles x 8 n-subtiles x 4 f32
    float cfr[2][8][4];
#pragma unroll
    for (int i = 0; i < 2; i++)
#pragma unroll
        for (int j = 0; j < 8; j++)
#pragma unroll
            for (int q = 0; q < 4; q++) cfr[i][j][q] = 0.f;

    const int wm0 = (wid >> 2) * 32;
    const int wn0 = (wid & 3) * 64;

    load_slab(0, 0);
    cp_commit();

    for (int s = 0; s < NS; s++) {
        const int cur = s & 1;
        cp_wait0();
        __syncthreads();
        if (s + 1 < NS) { load_slab(s + 1, cur ^ 1); cp_commit(); }

        const uint32_t abuf = base + cur * 16384;
        const uint32_t bbuf = base + 32768 + cur * 32768;
        const uint32_t arow = (uint32_t)(wm0 + (lane & 7) + ((lane >> 3) & 1) * 8);
        const uint32_t brow = (uint32_t)(wn0 + (lane & 7) + (lane >> 4) * 8);
#pragma unroll
        for (int ks = 0; ks < 4; ks++) {
            const uint32_t acol = (uint32_t)(ks * 16 + (lane >> 4) * 8) * 2;
            const uint32_t bcol = (uint32_t)(ks * 16 + ((lane >> 3) & 1) * 8) * 2;
            uint32_t a0[4], a1[4];
            ldsm4(a0, abuf + swz(arow * 128 + acol));
            ldsm4(a1, abuf + swz((arow + 16) * 128 + acol));
#pragma unroll
            for (int p = 0; p < 4; p++) {
                uint32_t b[4];
                ldsm4(b, bbuf + swz((brow + p * 16) * 128 + bcol));
                mma16816(cfr[0][2 * p],     a0, b);
                mma16816(cfr[0][2 * p + 1], a0, b + 2);
                mma16816(cfr[1][2 * p],     a1, b);
                mma16816(cfr[1][2 * p + 1], a1, b + 2);
            }
        }
    }
    __syncthreads();   // all mma done; smem buffers free for staging

    // ---- fused LSTM epilogue: two rounds of 64 pixels x 256 gates ----------
    float* zbuf = (float*)dptr;                 // 64*256 f32 = 64KB

    for (int r = 0; r < 2; r++) {
        if ((wm0 >> 6) == r) {
#pragma unroll
            for (int mi = 0; mi < 2; mi++) {
                int ml = (wm0 & 63) + mi * 16 + (lane >> 2);
#pragma unroll
                for (int nj = 0; nj < 8; nj++) {
                    int n = wn0 + nj * 8 + 2 * (lane & 3);
                    *(float2*)(zbuf + ml * 256 + n) =
                        make_float2(cfr[mi][nj][0], cfr[mi][nj][1]);
                    *(float2*)(zbuf + (ml + 8) * 256 + n) =
                        make_float2(cfr[mi][nj][2], cfr[mi][nj][3]);
                }
            }
        }
        __syncthreads();

        {   // gates: 64 pixels x 64 f; thread -> pixel p, 8 f values
            const int p = tid >> 3;
            const int f0 = (tid & 7) * 8;
            const int pix = m_tile + r * 64 + p;
            const float* zr = zbuf + p * 256;
            float cp8[8] = {0.f, 0.f, 0.f, 0.f, 0.f, 0.f, 0.f, 0.f};
            if (t > 0) {
                float4 c0 = *(const float4*)(g_c + (size_t)pix * 64 + f0);
                float4 c1 = *(const float4*)(g_c + (size_t)pix * 64 + f0 + 4);
                cp8[0] = c0.x; cp8[1] = c0.y; cp8[2] = c0.z; cp8[3] = c0.w;
                cp8[4] = c1.x; cp8[5] = c1.y; cp8[6] = c1.z; cp8[7] = c1.w;
            }
            float cn8[8], hn8[8];
#pragma unroll
            for (int j = 0; j < 8; j++) {
                int f = f0 + j;
                float vi = zr[f]       + s_bias[f];
                float vf = zr[64 + f]  + s_bias[64 + f];
                float vc = zr[128 + f] + s_bias[128 + f];
                float vo = zr[192 + f] + s_bias[192 + f];
                float cn = hsig(vf) * cp8[j] + hsig(vi) * fmaxf(vc, 0.f);
                cn8[j] = cn;
                hn8[j] = hsig(vo) * fmaxf(cn, 0.f);
            }
            if (last) {
                *(float4*)(out + (size_t)pix * 64 + f0) =
                    make_float4(hn8[0], hn8[1], hn8[2], hn8[3]);
                *(float4*)(out + (size_t)pix * 64 + f0 + 4) =
                    make_float4(hn8[4], hn8[5], hn8[6], hn8[7]);
            } else {
                *(float4*)(g_c + (size_t)pix * 64 + f0) =
                    make_float4(cn8[0], cn8[1], cn8[2], cn8[3]);
                *(float4*)(g_c + (size_t)pix * 64 + f0 + 4) =
                    make_float4(cn8[4], cn8[5], cn8[6], cn8[7]);
                // pack hi/lo splits in registers
                uint32_t ph[4], pl[4];
#pragma unroll
                for (int j2 = 0; j2 < 4; j2++) {
                    __half h0 = __float2half(hn8[2 * j2]);
                    __half h1 = __float2half(hn8[2 * j2 + 1]);
                    __half l0 = __float2half(hn8[2 * j2]     - __half2float(h0));
                    __half l1 = __float2half(hn8[2 * j2 + 1] - __half2float(h1));
                    ph[j2] = (uint32_t)__half_as_ushort(h0)
                           | ((uint32_t)__half_as_ushort(h1) << 16);
                    pl[j2] = (uint32_t)__half_as_ushort(l0)
                           | ((uint32_t)__half_as_ushort(l1) << 16);
                }
                uint4 vh = make_uint4(ph[0], ph[1], ph[2], ph[3]);
                uint4 vl = make_uint4(pl[0], pl[1], pl[2], pl[3]);
                *(uint4*)(h_wr + (size_t)pix * 192 + f0)       = vh;
                *(uint4*)(h_wr + (size_t)pix * 192 + 64 + f0)  = vh;
                *(uint4*)(h_wr + (size_t)pix * 192 + 128 + f0) = vl;
            }
        }
        __syncthreads();
    }
}

// ---------------------------------------------------------------------------

extern "C" void kernel_launch(void* const* d_in, const int* in_sizes, int n_in,
                              void* d_out, int out_size)
{
    const float* x    = (const float*)d_in[0];   // (8,16,64,64,32)
    const float* Wp   = (const float*)d_in[1];   // (3,3,32,256)
    const float* Up   = (const float*)d_in[2];   // (3,3,64,256)
    const float* bias = (const float*)d_in[3];   // (256,)
    float* out = (float*)d_out;                  // (8,64,64,64)

    cudaFuncSetAttribute(lstm_step_kernel,
                         cudaFuncAttributeMaxDynamicSharedMemorySize, 99328);

    wb_kernel<<<KALL2, 256>>>(Wp, Up);
    xs_kernel<<<65536, 256>>>(x);

    for (int t = 0; t < kT; t++)
        lstm_step_kernel<<<256, 512, 99328>>>(bias, out, t, t == kT - 1 ? 1 : 0);
}